// round 15
// baseline (speedup 1.0000x reference)
#include <cuda_runtime.h>
#include <math.h>

#define NN 50000
#define EE 800000
#define FF 100
#define HH 64
#define CC 40

// ---------------- scratch (device globals; referenced ONLY from device code) -
__device__ int   g_is64;                 // 1 if edge_index buffer is int64
__device__ int   g_deg[NN];
__device__ int   g_cur[NN];
__device__ int   g_off[NN + 1];
__device__ float g_dinv[NN];
__device__ int   g_col[EE];
__device__ float g_norm[EE];

// cat1 = [ U=x@W2 | Gp=x@W1 (-> G) | Y=x@(W0-W2) ]  stride 192
__device__ float g_cat1[(size_t)NN * 192];
// cat2 = [ U'=h@V2 | Gp'=h@V1 (-> G') | Y'=h@(V0-V2) | pad ] stride 128
__device__ float g_cat2[(size_t)NN * 128];
__device__ float g_h     [(size_t)NN * HH];
__device__ float g_logits[(size_t)NN * CC];
__device__ float g_Wcat1[100 * 192];
__device__ float g_Wcat2[64 * 128];      // pad cols 120:128 stay zero

// ---------------- dtype probe ------------------------------------------------
__global__ void probe_kernel(const int* __restrict__ ei32) {
    int allzero = 1;
    for (int k = 0; k < 256; k++)
        if (ei32[2 * k + 1] != 0) { allzero = 0; break; }
    g_is64 = allzero;
}

__device__ __forceinline__ int load_idx(const int* ei32, long long pos) {
    return g_is64 ? ei32[2 * pos] : ei32[pos];
}

// ---------------- CSR build --------------------------------------------------
__global__ void zero_kernel() {
    int i = blockIdx.x * blockDim.x + threadIdx.x;
    if (i < NN) { g_deg[i] = 0; g_cur[i] = 0; }
}

__global__ void hist_kernel(const int* __restrict__ ei32) {
    int e = blockIdx.x * blockDim.x + threadIdx.x;
    if (e < EE) {
        int r = load_idx(ei32, e);
        if (r >= 0 && r < NN) atomicAdd(&g_deg[r], 1);
    }
}

// fast single-block scan: thread-sequential chunks + shuffle scan of partials
__global__ void scan_kernel() {
    __shared__ int warpsum[32];
    const int tid  = threadIdx.x;          // 1024 threads
    const int lane = tid & 31, w = tid >> 5;
    const int CH = (NN + 1023) / 1024;     // 49
    int begin = tid * CH;
    int end   = begin + CH; if (end > NN) end = NN; if (begin > NN) begin = NN;

    int local = 0;
    for (int i = begin; i < end; i++) local += g_deg[i];

    int v = local;
    #pragma unroll
    for (int o = 1; o < 32; o <<= 1) {
        int t = __shfl_up_sync(0xffffffffu, v, o);
        if (lane >= o) v += t;
    }
    if (lane == 31) warpsum[w] = v;
    __syncthreads();
    if (w == 0) {
        int s = warpsum[lane];
        #pragma unroll
        for (int o = 1; o < 32; o <<= 1) {
            int t = __shfl_up_sync(0xffffffffu, s, o);
            if (lane >= o) s += t;
        }
        warpsum[lane] = s;
    }
    __syncthreads();

    int run = v - local + (w > 0 ? warpsum[w - 1] : 0);  // exclusive prefix
    for (int i = begin; i < end; i++) {
        int d = g_deg[i];
        g_off[i]  = run;
        g_dinv[i] = (d > 0) ? rsqrtf((float)d) : 0.0f;
        run += d;
    }
    if (tid == 1023) g_off[NN] = run;
}

__global__ void build_kernel(const int* __restrict__ ei32) {
    int e = blockIdx.x * blockDim.x + threadIdx.x;
    if (e < EE) {
        int r = load_idx(ei32, e);
        int c = load_idx(ei32, (long long)EE + e);
        if (r >= 0 && r < NN && c >= 0 && c < NN) {
            int p = g_off[r] + atomicAdd(&g_cur[r], 1);
            g_col[p]  = c;
            g_norm[p] = -g_dinv[r] * g_dinv[c];
        }
    }
}

// ---------------- weight concat prep ----------------------------------------
// W1 [3][100][64] -> Wcat1 [100][192] = [W2 | W1 | W0-W2]
__global__ void prep1_kernel(const float* __restrict__ W1) {
    int i = blockIdx.x * blockDim.x + threadIdx.x;
    if (i < 100 * 64) {
        int k = i / 64, j = i - k * 64;
        float w0 = W1[i], w1 = W1[6400 + i], w2 = W1[12800 + i];
        g_Wcat1[k * 192 + j]       = w2;
        g_Wcat1[k * 192 + 64 + j]  = w1;
        g_Wcat1[k * 192 + 128 + j] = w0 - w2;
    }
}
// W2 [3][64][40] -> Wcat2 [64][128] = [V2 | V1 | V0-V2 | 0pad]
__global__ void prep2_kernel(const float* __restrict__ W2) {
    int i = blockIdx.x * blockDim.x + threadIdx.x;
    if (i < 64 * 40) {
        int k = i / 40, j = i - k * 40;
        float v0 = W2[i], v1 = W2[2560 + i], v2 = W2[5120 + i];
        g_Wcat2[k * 128 + j]      = v2;
        g_Wcat2[k * 128 + 40 + j] = v1;
        g_Wcat2[k * 128 + 80 + j] = v0 - v2;
    }
}

// ---------------- GEMM: out[N,NC] = A[N,KTOT] @ Wc[KTOT,NC] ------------------
// 8x8 micro-tile, BM=64, NTH = 8*(NC/8)
template <int KTOT, int NC, int KC, bool L1>
__global__ void gemm_kernel(const float* __restrict__ Ain) {
    constexpr int BM  = 64;
    constexpr int NTH = 8 * (NC / 8);
    __shared__ __align__(16) float As[KC][BM];
    __shared__ __align__(16) float Ws[KC][NC];

    const float* A  = L1 ? Ain : (const float*)g_h;
    const float* Wc = L1 ? (const float*)g_Wcat1 : (const float*)g_Wcat2;
    float* out      = L1 ? g_cat1 : g_cat2;

    const int tid = threadIdx.x;
    const int tx  = tid % (NC / 8);       // col group
    const int ty  = tid / (NC / 8);       // row group 0..7
    const int r0  = blockIdx.x * BM;

    float acc[8][8];
    #pragma unroll
    for (int i = 0; i < 8; i++)
        #pragma unroll
        for (int j = 0; j < 8; j++) acc[i][j] = 0.0f;

    for (int k0 = 0; k0 < KTOT; k0 += KC) {
        for (int l = tid; l < BM * KC; l += NTH) {
            int row = l / KC;
            int kk  = l - row * KC;
            int r   = r0 + row;
            As[kk][row] = (r < NN) ? A[(size_t)r * KTOT + k0 + kk] : 0.0f;
        }
        for (int l = tid; l < KC * NC; l += NTH) {
            int kk = l / NC;
            int j  = l - kk * NC;
            Ws[kk][j] = Wc[(size_t)(k0 + kk) * NC + j];
        }
        __syncthreads();

        #pragma unroll
        for (int kk = 0; kk < KC; kk++) {
            float4 a0 = *(const float4*)&As[kk][ty * 8];
            float4 a1 = *(const float4*)&As[kk][ty * 8 + 4];
            float4 b0 = *(const float4*)&Ws[kk][tx * 8];
            float4 b1 = *(const float4*)&Ws[kk][tx * 8 + 4];
            float av[8] = {a0.x, a0.y, a0.z, a0.w, a1.x, a1.y, a1.z, a1.w};
            float bv[8] = {b0.x, b0.y, b0.z, b0.w, b1.x, b1.y, b1.z, b1.w};
            #pragma unroll
            for (int i = 0; i < 8; i++)
                #pragma unroll
                for (int j = 0; j < 8; j++)
                    acc[i][j] += av[i] * bv[j];
        }
        __syncthreads();
    }

    #pragma unroll
    for (int i = 0; i < 8; i++) {
        int r = r0 + ty * 8 + i;
        if (r < NN) {
            float* orow = out + (size_t)r * NC + tx * 8;
            #pragma unroll
            for (int j = 0; j < 8; j++) orow[j] = acc[i][j];
        }
    }
}

// ---------------- SpMV (warp per row) with fused epilogues -------------------
// MODE 0 (A): acc = L @ cat1[:,0:64]   ; cat1[r,64+f]  += 2*acc       (W=64)
// MODE 1 (B): acc = L @ cat1[:,64:128] ; h[r,f] = relu(cat1[r,128+f] + acc + b) (W=64)
// MODE 2 (C): acc = L @ cat2[:,0:40]   ; cat2[r,40+f]  += 2*acc       (W=40)
// MODE 3 (D): acc = L @ cat2[:,40:80]  ; logits[r,f] = cat2[r,80+f] + acc + b  (W=40)
template <int W, int MODE>
__global__ void spmv_kernel(const float* __restrict__ bias) {
    constexpr int SSTR = (MODE < 2) ? 192 : 128;
    constexpr int SOFF = (MODE == 0) ? 0 : (MODE == 1) ? 64 : (MODE == 2) ? 0 : 40;
    const float* base = (MODE < 2) ? (const float*)g_cat1 : (const float*)g_cat2;

    int warp = (blockIdx.x * blockDim.x + threadIdx.x) >> 5;
    int lane = threadIdx.x & 31;
    if (warp >= NN) return;

    constexpr int U = (W + 31) / 32;
    float acc[U];
    #pragma unroll
    for (int u = 0; u < U; u++) acc[u] = 0.0f;

    int s = g_off[warp];
    int e = g_off[warp + 1];
    for (int j = s; j < e; j++) {
        int   c = g_col[j];
        float w = g_norm[j];
        const float* sr = base + (size_t)c * SSTR + SOFF;
        #pragma unroll
        for (int u = 0; u < U; u++) {
            int f = lane + 32 * u;
            if (f < W) acc[u] += w * sr[f];
        }
    }

    #pragma unroll
    for (int u = 0; u < U; u++) {
        int f = lane + 32 * u;
        if (f < W) {
            if (MODE == 0) {
                float* p = g_cat1 + (size_t)warp * 192 + 64 + f;
                *p = *p + 2.0f * acc[u];
            } else if (MODE == 1) {
                float y = g_cat1[(size_t)warp * 192 + 128 + f];
                g_h[(size_t)warp * HH + f] = fmaxf(y + acc[u] + bias[f], 0.0f);
            } else if (MODE == 2) {
                float* p = g_cat2 + (size_t)warp * 128 + 40 + f;
                *p = *p + 2.0f * acc[u];
            } else {
                float y = g_cat2[(size_t)warp * 128 + 80 + f];
                g_logits[(size_t)warp * CC + f] = y + acc[u] + bias[f];
            }
        }
    }
}

// ---------------- log_softmax (warp per row, C = 40) -------------------------
__global__ void lsm_kernel(float* __restrict__ out) {
    int warp = (blockIdx.x * blockDim.x + threadIdx.x) >> 5;
    int lane = threadIdx.x & 31;
    if (warp >= NN) return;
    const float* r = g_logits + (size_t)warp * CC;

    float v0 = (lane < CC) ? r[lane] : -INFINITY;
    float v1 = (lane + 32 < CC) ? r[lane + 32] : -INFINITY;

    float m = fmaxf(v0, v1);
    #pragma unroll
    for (int o = 16; o; o >>= 1) m = fmaxf(m, __shfl_xor_sync(0xffffffffu, m, o));

    float s = 0.0f;
    if (lane < CC)      s += expf(v0 - m);
    if (lane + 32 < CC) s += expf(v1 - m);
    #pragma unroll
    for (int o = 16; o; o >>= 1) s += __shfl_xor_sync(0xffffffffu, s, o);

    float lse = m + logf(s);
    float* orow = out + (size_t)warp * CC;
    if (lane < CC)      orow[lane]      = v0 - lse;
    if (lane + 32 < CC) orow[lane + 32] = v1 - lse;
}

// ---------------- launch -----------------------------------------------------
extern "C" void kernel_launch(void* const* d_in, const int* in_sizes, int n_in,
                              void* d_out, int out_size) {
    const float* x  = (const float*)d_in[0];
    const int*   ei = (const int*)d_in[1];        // raw words; dtype probed on device
    const float* W1 = (const float*)d_in[2];      // [3,100,64]
    const float* b1 = (const float*)d_in[3];
    const float* W2 = (const float*)d_in[4];      // [3,64,40]
    const float* b2 = (const float*)d_in[5];
    float*       out = (float*)d_out;

    // dtype probe + CSR build + weight prep
    probe_kernel<<<1, 1>>>(ei);
    zero_kernel<<<(NN + 255) / 256, 256>>>();
    hist_kernel<<<(EE + 255) / 256, 256>>>(ei);
    scan_kernel<<<1, 1024>>>();
    build_kernel<<<(EE + 255) / 256, 256>>>(ei);
    prep1_kernel<<<(100 * 64 + 255) / 256, 256>>>(W1);
    prep2_kernel<<<(64 * 40 + 255) / 256, 256>>>(W2);

    const int SPMV_BLK  = 256;
    const int spmv_grid = (NN * 32 + SPMV_BLK - 1) / SPMV_BLK;
    const int gemm_grid = (NN + 63) / 64;

    // Layer 1: cat1 = x @ [W2|W1|W0-W2]; G = Gp + 2 L U; h = relu(Y + L G + b1)
    gemm_kernel<FF, 192, 20, true><<<gemm_grid, 192>>>(x);
    spmv_kernel<64, 0><<<spmv_grid, SPMV_BLK>>>(nullptr);
    spmv_kernel<64, 1><<<spmv_grid, SPMV_BLK>>>(b1);

    // Layer 2: cat2 = h @ [V2|V1|V0-V2|0]; G' = Gp' + 2 L U'; logits = Y' + L G' + b2
    gemm_kernel<HH, 128, 16, false><<<gemm_grid, 128>>>(nullptr);
    spmv_kernel<40, 2><<<spmv_grid, SPMV_BLK>>>(nullptr);
    spmv_kernel<40, 3><<<spmv_grid, SPMV_BLK>>>(b2);

    // out = log_softmax(logits)
    lsm_kernel<<<spmv_grid, SPMV_BLK>>>(out);
}

// round 16
// speedup vs baseline: 1.3058x; 1.3058x over previous
#include <cuda_runtime.h>
#include <math.h>

#define NN 50000
#define EE 800000
#define FF 100
#define HH 64
#define CC 40

#define SCAN_BLK 512
#define SCAN_NBLK ((NN + SCAN_BLK - 1) / SCAN_BLK)   // 98

// ---------------- scratch (device globals; referenced ONLY from device code) -
__device__ int   g_is64;                 // 1 if edge_index buffer is int64
__device__ int   g_deg[NN];
__device__ int   g_cur[NN];
__device__ int   g_off[NN + 1];
__device__ int   g_part[SCAN_NBLK];
__device__ float g_dinv[NN];
__device__ int   g_col[EE];
__device__ float g_norm[EE];

__device__ float g_Tx1 [(size_t)NN * FF];
__device__ float g_Tx2 [(size_t)NN * FF];
__device__ float g_h   [(size_t)NN * HH];
__device__ float g_hTx1[(size_t)NN * HH];
__device__ float g_hTx2[(size_t)NN * HH];
__device__ float g_logits[(size_t)NN * CC];

// ---------------- dtype probe ------------------------------------------------
__global__ void probe_kernel(const int* __restrict__ ei32) {
    int allzero = 1;
    for (int k = 0; k < 256; k++)
        if (ei32[2 * k + 1] != 0) { allzero = 0; break; }
    g_is64 = allzero;
}

__device__ __forceinline__ int load_idx(const int* ei32, long long pos) {
    return g_is64 ? ei32[2 * pos] : ei32[pos];
}

// ---------------- CSR build --------------------------------------------------
__global__ void zero_kernel() {
    int i = blockIdx.x * blockDim.x + threadIdx.x;
    if (i < NN) { g_deg[i] = 0; g_cur[i] = 0; }
}

__global__ void hist_kernel(const int* __restrict__ ei32) {
    int e = blockIdx.x * blockDim.x + threadIdx.x;
    if (e < EE) {
        int r = load_idx(ei32, e);
        if (r >= 0 && r < NN) atomicAdd(&g_deg[r], 1);
    }
}

// ---- 3-phase coalesced scan -------------------------------------------------
// Phase 1: per-block sums (coalesced)
__global__ void scan_reduce_kernel() {
    __shared__ int ws[SCAN_BLK / 32];
    int tid  = threadIdx.x;
    int lane = tid & 31, w = tid >> 5;
    int i = blockIdx.x * SCAN_BLK + tid;
    int v = (i < NN) ? g_deg[i] : 0;
    #pragma unroll
    for (int o = 16; o; o >>= 1) v += __shfl_down_sync(0xffffffffu, v, o);
    if (lane == 0) ws[w] = v;
    __syncthreads();
    if (w == 0) {
        int u = (lane < SCAN_BLK / 32) ? ws[lane] : 0;
        #pragma unroll
        for (int o = 8; o; o >>= 1) u += __shfl_down_sync(0xffffffffu, u, o);
        if (lane == 0) g_part[blockIdx.x] = u;
    }
}

// Phase 2: single block scans the 98 partials (exclusive, in place)
__global__ void scan_part_kernel() {
    __shared__ int sh[128];
    int tid = threadIdx.x;                 // 128 threads
    int v = (tid < SCAN_NBLK) ? g_part[tid] : 0;
    sh[tid] = v;
    __syncthreads();
    #pragma unroll
    for (int o = 1; o < 128; o <<= 1) {
        int t = (tid >= o) ? sh[tid - o] : 0;
        __syncthreads();
        sh[tid] += t;
        __syncthreads();
    }
    if (tid < SCAN_NBLK) g_part[tid] = sh[tid] - v;   // exclusive
    if (tid == 127) g_off[NN] = sh[127];              // total edge count
}

// Phase 3: per-block exclusive scan + scatter (coalesced)
__global__ void scan_scatter_kernel() {
    __shared__ int ws[SCAN_BLK / 32];
    int tid  = threadIdx.x;
    int lane = tid & 31, w = tid >> 5;
    int i = blockIdx.x * SCAN_BLK + tid;
    int d = (i < NN) ? g_deg[i] : 0;

    int v = d;
    #pragma unroll
    for (int o = 1; o < 32; o <<= 1) {
        int t = __shfl_up_sync(0xffffffffu, v, o);
        if (lane >= o) v += t;
    }
    if (lane == 31) ws[w] = v;
    __syncthreads();
    if (w == 0) {
        int u = (lane < SCAN_BLK / 32) ? ws[lane] : 0;
        #pragma unroll
        for (int o = 1; o < SCAN_BLK / 32; o <<= 1) {
            int t = __shfl_up_sync(0xffffffffu, u, o);
            if (lane >= o) u += t;
        }
        if (lane < SCAN_BLK / 32) ws[lane] = u;
    }
    __syncthreads();

    if (i < NN) {
        int excl = v - d + (w > 0 ? ws[w - 1] : 0) + g_part[blockIdx.x];
        g_off[i]  = excl;
        g_dinv[i] = (d > 0) ? rsqrtf((float)d) : 0.0f;
    }
}

__global__ void build_kernel(const int* __restrict__ ei32) {
    int e = blockIdx.x * blockDim.x + threadIdx.x;
    if (e < EE) {
        int r = load_idx(ei32, e);
        int c = load_idx(ei32, (long long)EE + e);
        if (r >= 0 && r < NN && c >= 0 && c < NN) {
            int p = g_off[r] + atomicAdd(&g_cur[r], 1);
            g_col[p]  = c;
            g_norm[p] = -g_dinv[r] * g_dinv[c];
        }
    }
}

// ---------------- SpMV -------------------------------------------------------
// MODE 0: g_Tx1  = L @ x                (src = xin,   W = FF)
// MODE 1: g_Tx2  = 2 L @ g_Tx1  - x    (other = xin, W = FF)
// MODE 2: g_hTx1 = L @ g_h              (W = HH)
// MODE 3: g_hTx2 = 2 L @ g_hTx1 - g_h  (W = HH)
template <int W, int MODE>
__global__ void spmv_kernel(const float* __restrict__ xin) {
    const float* src   = (MODE == 0) ? xin
                       : (MODE == 1) ? (const float*)g_Tx1
                       : (MODE == 2) ? (const float*)g_h
                                     : (const float*)g_hTx1;
    const float* other = (MODE == 1) ? xin
                       : (MODE == 3) ? (const float*)g_h
                                     : nullptr;
    float* dst         = (MODE == 0) ? g_Tx1
                       : (MODE == 1) ? g_Tx2
                       : (MODE == 2) ? g_hTx1
                                     : g_hTx2;
    const float alpha  = (MODE == 1 || MODE == 3) ? 2.0f : 1.0f;

    int warp = (blockIdx.x * blockDim.x + threadIdx.x) >> 5;
    int lane = threadIdx.x & 31;
    if (warp >= NN) return;

    constexpr int U = (W + 31) / 32;
    float acc[U];
    #pragma unroll
    for (int u = 0; u < U; u++) acc[u] = 0.0f;

    int s = g_off[warp];
    int e = g_off[warp + 1];
    for (int j = s; j < e; j++) {
        int   c = g_col[j];
        float w = g_norm[j];
        const float* sr = src + (size_t)c * W;
        #pragma unroll
        for (int u = 0; u < U; u++) {
            int f = lane + 32 * u;
            if (f < W) acc[u] += w * sr[f];
        }
    }

    float* dr = dst + (size_t)warp * W;
    #pragma unroll
    for (int u = 0; u < U; u++) {
        int f = lane + 32 * u;
        if (f < W) {
            float v = alpha * acc[u];
            if (MODE == 1 || MODE == 3) v -= other[(size_t)warp * W + f];
            dr[f] = v;
        }
    }
}

// ---------------- fused 3-way GEMM: out = act([A0|A1|A2] @ W + bias) ---------
template <int FW, int NC, int KC, bool L1>
__global__ void gemm3_kernel(const float* __restrict__ xin,
                             const float* __restrict__ Wt,
                             const float* __restrict__ bias) {
    constexpr int BM = 64;
    constexpr int KTOT = 3 * FW;
    __shared__ __align__(16) float As[KC][BM];
    __shared__ __align__(16) float Ws[KC][NC];

    const int tx  = threadIdx.x;          // 0 .. NC/4-1
    const int ty  = threadIdx.y;          // 0 .. 15
    const int tid = ty * blockDim.x + tx;
    const int nth = blockDim.x * blockDim.y;
    const int r0  = blockIdx.x * BM;

    const float* srcs[3];
    srcs[0] = L1 ? xin : (const float*)g_h;
    srcs[1] = L1 ? (const float*)g_Tx1 : (const float*)g_hTx1;
    srcs[2] = L1 ? (const float*)g_Tx2 : (const float*)g_hTx2;
    float* out = L1 ? g_h : g_logits;

    float acc[4][4];
    #pragma unroll
    for (int i = 0; i < 4; i++)
        #pragma unroll
        for (int j = 0; j < 4; j++) acc[i][j] = 0.0f;

    for (int k0 = 0; k0 < KTOT; k0 += KC) {
        for (int l = tid; l < BM * KC; l += nth) {
            int row = l / KC;
            int kk  = l - row * KC;
            int kg  = k0 + kk;
            int sidx = kg / FW;
            int f    = kg - sidx * FW;
            int r    = r0 + row;
            As[kk][row] = (r < NN) ? srcs[sidx][(size_t)r * FW + f] : 0.0f;
        }
        for (int l = tid; l < KC * NC; l += nth) {
            int kk = l / NC;
            int j  = l - kk * NC;
            Ws[kk][j] = Wt[(size_t)(k0 + kk) * NC + j];
        }
        __syncthreads();

        #pragma unroll
        for (int kk = 0; kk < KC; kk++) {
            float4 a4 = *(const float4*)&As[kk][ty * 4];
            float4 b4 = *(const float4*)&Ws[kk][tx * 4];
            float av[4] = {a4.x, a4.y, a4.z, a4.w};
            float bv[4] = {b4.x, b4.y, b4.z, b4.w};
            #pragma unroll
            for (int i = 0; i < 4; i++)
                #pragma unroll
                for (int j = 0; j < 4; j++)
                    acc[i][j] += av[i] * bv[j];
        }
        __syncthreads();
    }

    #pragma unroll
    for (int i = 0; i < 4; i++) {
        int r = r0 + ty * 4 + i;
        if (r < NN) {
            #pragma unroll
            for (int j = 0; j < 4; j++) {
                float v = acc[i][j] + bias[tx * 4 + j];
                if (L1) v = fmaxf(v, 0.0f);          // relu only on layer 1
                out[(size_t)r * NC + tx * 4 + j] = v;
            }
        }
    }
}

// ---------------- log_softmax (warp per row, C = 40) -------------------------
__global__ void lsm_kernel(float* __restrict__ out) {
    int warp = (blockIdx.x * blockDim.x + threadIdx.x) >> 5;
    int lane = threadIdx.x & 31;
    if (warp >= NN) return;
    const float* r = g_logits + (size_t)warp * CC;

    float v0 = (lane < CC) ? r[lane] : -INFINITY;
    float v1 = (lane + 32 < CC) ? r[lane + 32] : -INFINITY;

    float m = fmaxf(v0, v1);
    #pragma unroll
    for (int o = 16; o; o >>= 1) m = fmaxf(m, __shfl_xor_sync(0xffffffffu, m, o));

    float s = 0.0f;
    if (lane < CC)      s += expf(v0 - m);
    if (lane + 32 < CC) s += expf(v1 - m);
    #pragma unroll
    for (int o = 16; o; o >>= 1) s += __shfl_xor_sync(0xffffffffu, s, o);

    float lse = m + logf(s);
    float* orow = out + (size_t)warp * CC;
    if (lane < CC)      orow[lane]      = v0 - lse;
    if (lane + 32 < CC) orow[lane + 32] = v1 - lse;
}

// ---------------- launch -----------------------------------------------------
extern "C" void kernel_launch(void* const* d_in, const int* in_sizes, int n_in,
                              void* d_out, int out_size) {
    const float* x  = (const float*)d_in[0];
    const int*   ei = (const int*)d_in[1];        // raw words; dtype probed on device
    const float* W1 = (const float*)d_in[2];      // [3,100,64] == [300][64]
    const float* b1 = (const float*)d_in[3];
    const float* W2 = (const float*)d_in[4];      // [3,64,40]  == [192][40]
    const float* b2 = (const float*)d_in[5];
    float*       out = (float*)d_out;

    // dtype probe + CSR build
    probe_kernel<<<1, 1>>>(ei);
    zero_kernel<<<(NN + 255) / 256, 256>>>();
    hist_kernel<<<(EE + 255) / 256, 256>>>(ei);
    scan_reduce_kernel<<<SCAN_NBLK, SCAN_BLK>>>();
    scan_part_kernel<<<1, 128>>>();
    scan_scatter_kernel<<<SCAN_NBLK, SCAN_BLK>>>();
    build_kernel<<<(EE + 255) / 256, 256>>>(ei);

    const int SPMV_BLK = 256;                          // 8 warps / block
    const int spmv_grid = (NN * 32 + SPMV_BLK - 1) / SPMV_BLK;

    // Layer 1: Tx1 = L x ; Tx2 = 2 L Tx1 - x
    spmv_kernel<FF, 0><<<spmv_grid, SPMV_BLK>>>(x);
    spmv_kernel<FF, 1><<<spmv_grid, SPMV_BLK>>>(x);

    // h = relu([x|Tx1|Tx2] @ W1 + b1)
    {
        dim3 blk(HH / 4, 16);
        int grid = (NN + 63) / 64;
        gemm3_kernel<FF, HH, 20, true><<<grid, blk>>>(x, W1, b1);
    }

    // Layer 2: hTx1 = L h ; hTx2 = 2 L hTx1 - h
    spmv_kernel<HH, 2><<<spmv_grid, SPMV_BLK>>>(nullptr);
    spmv_kernel<HH, 3><<<spmv_grid, SPMV_BLK>>>(nullptr);

    // logits = [h|hTx1|hTx2] @ W2 + b2
    {
        dim3 blk(CC / 4, 16);
        int grid = (NN + 63) / 64;
        gemm3_kernel<HH, CC, 16, false><<<grid, blk>>>(nullptr, W2, b2);
    }

    // out = log_softmax(logits)
    lsm_kernel<<<spmv_grid, SPMV_BLK>>>(out);
}